// round 10
// baseline (speedup 1.0000x reference)
#include <cuda_runtime.h>
#include <cuda_fp16.h>
#include <cstdint>

// ============================================================================
// ConditionEmbedder — sm_103 mma.sync.m16n8k16, v5.
// R10 vs R9 (166.4us): kout halves split across WARPS (0-3 -> cols 0-63,
// 4-7 -> cols 64-127) on a 64-row CTA instead of across time. Softmax per
// (row,d) computed ONCE (8 rows/warp), normalized fp16 fragments stored to a
// smem A-tile, both half-warps reload them via ldmatrix. Halves total exp
// work (268M -> 134M ex2) and kills the afr[32] register array. acc[32]
// unchanged, 2 CTA/SM unchanged.
// ============================================================================

static constexpr int DDIMS        = 8;
static constexpr int HDIM         = 128;
static constexpr int ROWS_PER_CTA = 64;
static constexpr int NBLOCKS      = 131072 / ROWS_PER_CTA;   // 2048
static constexpr int CTA_THREADS  = 256;                     // 8 warps

static constexpr int BROW_BYTES   = 272;                     // 256 + 16B pad
static constexpr int ATILE_BYTES  = 64  * BROW_BYTES;        // 17408
static constexpr int BTILE_BYTES  = 128 * BROW_BYTES;        // 34816 (full w2[d])

// smem layout (dynamic)
static constexpr int SMEM_LABELS  = 0;                       // 64*8*4 = 2048
static constexpr int SMEM_EMB     = 2048;                    // 4096
static constexpr int SMEM_PK      = 6144;                    // 8192
static constexpr int SMEM_STATS   = 14336;                   // 128
static constexpr int SMEM_NMASK   = 14464;                   // 64*4 = 256
static constexpr int SMEM_A       = 14720;                   // 17408
static constexpr int SMEM_BT0     = 32128;                   // 34816
static constexpr int SMEM_BT1     = 66944;                   // 34816
static constexpr int SMEM_TOTAL   = 101760;                  // x2 CTA = 203.5KB

// Pre-converted fp16 w2, [d][k_out][h] row-major (== col-major B for the mma).
__device__ __align__(16) __half g_w2h[DDIMS * HDIM * HDIM];
// Fragment-ordered, log2e-scaled w1/b1: (d,t,q) -> cols {cb,cb+1,cb+8,cb+9},
// cb = 16t+2q. [0..255] = w, [256..511] = b.
__device__ __align__(16) float4 g_pk[512];
// Per-dim stats: [0..7] max(w1L), [8..15] min(w1L), [16..23] max(b1L)
__device__ float g_st[24];

__global__ void prep_w2_kernel(const float* __restrict__ w2) {
    int i = blockIdx.x * 256 + threadIdx.x;      // exactly 131072 elements
    g_w2h[i] = __float2half(w2[i]);
}

// 256 threads: lane l of warp d handles (t = l>>2, q = l&3).
__global__ void prep_small_kernel(const float* __restrict__ w1,
                                  const float* __restrict__ b1) {
    const int tid  = threadIdx.x;
    const int d    = tid >> 5;
    const int lane = tid & 31;
    const int t    = lane >> 2;
    const int q    = lane & 3;
    const int cb   = 16 * t + 2 * q;
    const float LOG2E = 1.44269504088896340736f;

    float w0  = w1[d * HDIM + cb]     * LOG2E;
    float w1v = w1[d * HDIM + cb + 1] * LOG2E;
    float w8  = w1[d * HDIM + cb + 8] * LOG2E;
    float w9  = w1[d * HDIM + cb + 9] * LOG2E;
    float bb0 = b1[d * HDIM + cb]     * LOG2E;
    float bb1 = b1[d * HDIM + cb + 1] * LOG2E;
    float bb8 = b1[d * HDIM + cb + 8] * LOG2E;
    float bb9 = b1[d * HDIM + cb + 9] * LOG2E;

    const int e = (d * 8 + t) * 4 + q;
    g_pk[e]       = make_float4(w0, w1v, w8, w9);
    g_pk[256 + e] = make_float4(bb0, bb1, bb8, bb9);

    float hi = fmaxf(fmaxf(w0, w1v), fmaxf(w8, w9));
    float lo = fminf(fminf(w0, w1v), fminf(w8, w9));
    float bm = fmaxf(fmaxf(bb0, bb1), fmaxf(bb8, bb9));
    #pragma unroll
    for (int s = 16; s; s >>= 1) {
        hi = fmaxf(hi, __shfl_xor_sync(0xffffffffu, hi, s));
        lo = fminf(lo, __shfl_xor_sync(0xffffffffu, lo, s));
        bm = fmaxf(bm, __shfl_xor_sync(0xffffffffu, bm, s));
    }
    if (lane == 0) { g_st[d] = hi; g_st[8 + d] = lo; g_st[16 + d] = bm; }
}

__device__ __forceinline__ uint32_t smem_to_u32(const void* p) {
    uint32_t a;
    asm("{ .reg .u64 t; cvta.to.shared.u64 t, %1; cvt.u32.u64 %0, t; }"
        : "=r"(a) : "l"(p));
    return a;
}

__device__ __forceinline__ float ex2f(float x) {
    float r;
    asm("ex2.approx.ftz.f32 %0, %1;" : "=f"(r) : "f"(x));
    return r;
}

__device__ __forceinline__ void cp_async16(uint32_t dst, const void* src) {
    asm volatile("cp.async.cg.shared.global [%0], [%1], 16;"
                 :: "r"(dst), "l"(src));
}

__global__ void __launch_bounds__(CTA_THREADS, 2)
cond_embed_kernel(const float* __restrict__ labels,
                  const float* __restrict__ emb_w,
                  const int*   __restrict__ uncond_p,
                  float*       __restrict__ out)
{
    extern __shared__ __align__(16) char smem[];
    float*  lab_sm = reinterpret_cast<float*>(smem + SMEM_LABELS);
    float*  emb_sm = reinterpret_cast<float*>(smem + SMEM_EMB);
    float4* pk_sm  = reinterpret_cast<float4*>(smem + SMEM_PK);
    float*  st_sm  = reinterpret_cast<float*>(smem + SMEM_STATS);
    int*    nm_sm  = reinterpret_cast<int*>(smem + SMEM_NMASK);

    const int tid  = threadIdx.x;
    const int wid  = tid >> 5;
    const int lane = tid & 31;
    const int gr   = lane >> 2;
    const int q    = lane & 3;
    const int blk  = blockIdx.x;

    const uint32_t smem_base = smem_to_u32(smem);

    // ---- stage labels + emb + pk + stats; B(0) (full 32KB) via cp.async ----
    for (int i = tid; i < 512; i += CTA_THREADS)
        lab_sm[i] = labels[(size_t)blk * 512 + i];
    for (int i = tid; i < 1024; i += CTA_THREADS)
        emb_sm[i] = emb_w[i];
    for (int i = tid; i < 512; i += CTA_THREADS)
        pk_sm[i] = g_pk[i];
    if (tid < 24) st_sm[tid] = g_st[tid];
    {
        const char* src = reinterpret_cast<const char*>(g_w2h);
        #pragma unroll
        for (int i = 0; i < 8; ++i) {
            int idx = tid + i * CTA_THREADS;      // 0..2047, 16B lines
            cp_async16(smem_base + SMEM_BT0 + (idx >> 4) * BROW_BYTES
                       + (idx & 15) * 16, src + idx * 16);
        }
        asm volatile("cp.async.commit_group;" ::: "memory");
    }
    const int force_drop = *uncond_p;

    float acc[32];
    #pragma unroll
    for (int i = 0; i < 32; ++i) acc[i] = 0.0f;

    unsigned mask = 0;                         // drop bits for row srow
    const int srow  = 8 * wid + gr;            // softmax row owned by this lane
    const int nh    = wid >> 2;                // output-column half of this warp
    const int mrow0 = 16 * (wid & 3);          // mma M-tile start row

    // ldmatrix lane bases
    const uint32_t a_lm = smem_base + SMEM_A
        + (uint32_t)(mrow0 + (lane & 15)) * BROW_BYTES
        + (uint32_t)((lane >> 4) & 1) * 16u;
    const uint32_t b_lm = smem_base + SMEM_BT0
        + (uint32_t)nh * (64u * BROW_BYTES)
        + ((uint32_t)(lane >> 4) * 8u + (uint32_t)(lane & 7)) * BROW_BYTES
        + (uint32_t)((lane >> 3) & 1) * 16u;
    // softmax fragment store base: row srow, byte cols 32t+4q (+16)
    const uint32_t a_st = smem_base + SMEM_A
        + (uint32_t)srow * BROW_BYTES + (uint32_t)(4 * q);

    asm volatile("cp.async.wait_group 0;" ::: "memory");   // B(0)
    __syncthreads();

    for (int d = 0; d < DDIMS; ++d) {
        // ---- 1. softmax for row srow -> 16 packed fp16x2 regs (once!) ----
        uint32_t pk16[16];
        float inv;
        {
            const float x = lab_sm[srow * DDIMS + d];
            const bool dr = ((__float_as_uint(x) & 0x7fffffffu) > 0x7f800000u)
                            || force_drop;
            if (dr) mask |= 1u << d;
            const float xs = dr ? 0.0f : x;
            const float hiL = st_sm[d], loL = st_sm[8 + d], bmL = st_sm[16 + d];
            const float ub = fmaf(xs, xs >= 0.0f ? hiL : loL, bmL);
            const float4* pw = pk_sm + d * 32 + q;
            const float4* pb = pw + 256;
            float z = 0.0f;
            #pragma unroll
            for (int t = 0; t < 8; ++t) {
                const float4 wv = pw[t * 4];
                const float4 bv = pb[t * 4];
                float e0 = ex2f(fmaf(xs, wv.x, bv.x) - ub);
                float e1 = ex2f(fmaf(xs, wv.y, bv.y) - ub);
                float e2 = ex2f(fmaf(xs, wv.z, bv.z) - ub);
                float e3 = ex2f(fmaf(xs, wv.w, bv.w) - ub);
                z += (e0 + e1) + (e2 + e3);
                __half2 plo = __floats2half2_rn(e0, e1);
                __half2 phi = __floats2half2_rn(e2, e3);
                pk16[2 * t]     = *reinterpret_cast<uint32_t*>(&plo);
                pk16[2 * t + 1] = *reinterpret_cast<uint32_t*>(&phi);
            }
            z += __shfl_xor_sync(0xffffffffu, z, 1);
            z += __shfl_xor_sync(0xffffffffu, z, 2);
            inv = dr ? 0.0f : __fdividef(1.0f, z);
        }
        {
            const __half2 iv = __half2half2(__float2half_rn(inv));
            #pragma unroll
            for (int t = 0; t < 16; ++t) {
                __half2* a = reinterpret_cast<__half2*>(pk16 + t);
                *a = __hmul2(*a, iv);
            }
        }

        __syncthreads();   // everyone finished ldmatrix of A(d-1)/B(d-1)

        // ---- 2. store A(d) fragments (conflict-free) ----
        #pragma unroll
        for (int t = 0; t < 8; ++t) {
            asm volatile("st.shared.u32 [%0], %1;"
                         :: "r"(a_st + (uint32_t)(32 * t)), "r"(pk16[2 * t]));
            asm volatile("st.shared.u32 [%0], %1;"
                         :: "r"(a_st + (uint32_t)(32 * t + 16)), "r"(pk16[2 * t + 1]));
        }

        // ---- 3. stage B(d+1) full tile into alt buffer; ensure B(d) landed ----
        if (d < DDIMS - 1) {
            const char* src = reinterpret_cast<const char*>(g_w2h + (d + 1) * HDIM * HDIM);
            const uint32_t dstb = smem_base + ((d + 1) & 1 ? SMEM_BT1 : SMEM_BT0);
            #pragma unroll
            for (int i = 0; i < 8; ++i) {
                int idx = tid + i * CTA_THREADS;
                cp_async16(dstb + (idx >> 4) * BROW_BYTES + (idx & 15) * 16,
                           src + idx * 16);
            }
            asm volatile("cp.async.commit_group;" ::: "memory");
            asm volatile("cp.async.wait_group 1;" ::: "memory");   // B(d) done
        } else {
            asm volatile("cp.async.wait_group 0;" ::: "memory");   // B(7) done
        }

        __syncthreads();   // A(d) + B(d) visible to all warps

        // ---- 4. D += A(d) @ B(d)^T : 8 k-chunks, A via ldmatrix JIT ----
        const uint32_t bb = b_lm + (uint32_t)(d & 1) * BTILE_BYTES;
        #pragma unroll
        for (int t = 0; t < 8; ++t) {
            uint32_t af0, af1, af2, af3;
            asm volatile(
                "ldmatrix.sync.aligned.m8n8.x4.shared.b16 {%0,%1,%2,%3}, [%4];"
                : "=r"(af0), "=r"(af1), "=r"(af2), "=r"(af3)
                : "r"(a_lm + (uint32_t)t * 32u));
            #pragma unroll
            for (int p = 0; p < 4; ++p) {
                uint32_t bf0, bf1, bf2, bf3;
                asm volatile(
                    "ldmatrix.sync.aligned.m8n8.x4.shared.b16 {%0,%1,%2,%3}, [%4];"
                    : "=r"(bf0), "=r"(bf1), "=r"(bf2), "=r"(bf3)
                    : "r"(bb + (uint32_t)p * (16u * BROW_BYTES) + (uint32_t)t * 32u));
                asm volatile(
                    "mma.sync.aligned.m16n8k16.row.col.f32.f16.f16.f32 "
                    "{%0,%1,%2,%3}, {%4,%5,%6,%7}, {%8,%9}, {%0,%1,%2,%3};"
                    : "+f"(acc[8*p+0]), "+f"(acc[8*p+1]), "+f"(acc[8*p+2]), "+f"(acc[8*p+3])
                    : "r"(af0), "r"(af1), "r"(af2), "r"(af3), "r"(bf0), "r"(bf1));
                asm volatile(
                    "mma.sync.aligned.m16n8k16.row.col.f32.f16.f16.f32 "
                    "{%0,%1,%2,%3}, {%4,%5,%6,%7}, {%8,%9}, {%0,%1,%2,%3};"
                    : "+f"(acc[8*p+4]), "+f"(acc[8*p+5]), "+f"(acc[8*p+6]), "+f"(acc[8*p+7])
                    : "r"(af0), "r"(af1), "r"(af2), "r"(af3), "r"(bf2), "r"(bf3));
            }
        }
    }

    // ---- publish drop masks, then epilogue ----
    if (q == 0) nm_sm[srow] = (int)mask;
    __syncthreads();

    const unsigned m0 = (unsigned)nm_sm[mrow0 + gr];
    const unsigned m1 = (unsigned)nm_sm[mrow0 + gr + 8];
    const size_t base0 = ((size_t)blk * ROWS_PER_CTA + mrow0 + gr) * HDIM + nh * 64;
    const size_t base1 = base0 + 8 * HDIM;
    #pragma unroll
    for (int p = 0; p < 4; ++p) {
        #pragma unroll
        for (int h = 0; h < 2; ++h) {            // nt = 2p+h
            const int c  = (2 * p + h) * 8 + 2 * q;
            const int ce = nh * 64 + c;
            float v0 = acc[8*p + 4*h + 0], v1 = acc[8*p + 4*h + 1];
            float v2 = acc[8*p + 4*h + 2], v3 = acc[8*p + 4*h + 3];
            unsigned m = m0;
            while (m) {
                const int dd = __ffs(m) - 1; m &= m - 1;
                v0 += emb_sm[dd * HDIM + ce];
                v1 += emb_sm[dd * HDIM + ce + 1];
            }
            m = m1;
            while (m) {
                const int dd = __ffs(m) - 1; m &= m - 1;
                v2 += emb_sm[dd * HDIM + ce];
                v3 += emb_sm[dd * HDIM + ce + 1];
            }
            *reinterpret_cast<float2*>(out + base0 + c) = make_float2(v0, v1);
            *reinterpret_cast<float2*>(out + base1 + c) = make_float2(v2, v3);
        }
    }
}

// ============================================================================
// kernel_launch — inputs: labels, emb_w, w1, b1, w2, train, unconditioned
//                 output: float32 [131072, 128]
// ============================================================================
extern "C" void kernel_launch(void* const* d_in, const int* in_sizes, int n_in,
                              void* d_out, int out_size)
{
    const float* labels = (const float*)d_in[0];
    const float* emb_w  = (const float*)d_in[1];
    const float* w1     = (const float*)d_in[2];
    const float* b1     = (const float*)d_in[3];
    const float* w2     = (const float*)d_in[4];
    const int*   uncond = (n_in > 6) ? (const int*)d_in[6] : (const int*)d_in[5];
    float* out = (float*)d_out;

    prep_w2_kernel<<<DDIMS * HDIM * HDIM / 256, 256>>>(w2);
    prep_small_kernel<<<1, 256>>>(w1, b1);

    cudaFuncSetAttribute(cond_embed_kernel,
                         cudaFuncAttributeMaxDynamicSharedMemorySize, SMEM_TOTAL);
    cond_embed_kernel<<<NBLOCKS, CTA_THREADS, SMEM_TOTAL>>>(
        labels, emb_w, uncond, out);
}

// round 11
// speedup vs baseline: 1.0069x; 1.0069x over previous
#include <cuda_runtime.h>
#include <cuda_fp16.h>
#include <cstdint>

// ============================================================================
// ConditionEmbedder — sm_103 mma.sync.m16n8k16, v6.
// R11 = R10's softmax-once warp-split, re-tiled to fix its regressions:
// ONE 512-thread CTA per 128 batch rows (16 warps; warps 0-7 -> cols 0-63,
// 8-15 -> cols 64-127). B staging back to 256MB total (R9 level), 1024 CTAs
// (R9 level), exp work stays halved (134M ex2). cp.async for B(d+1) issued
// BEFORE the softmax phase so global latency hides under MUFU work.
// ============================================================================

static constexpr int DDIMS        = 8;
static constexpr int HDIM         = 128;
static constexpr int ROWS_PER_CTA = 128;
static constexpr int NBLOCKS      = 131072 / ROWS_PER_CTA;   // 1024
static constexpr int CTA_THREADS  = 512;                     // 16 warps

static constexpr int BROW_BYTES   = 272;                     // 256 + 16B pad
static constexpr int BTILE_BYTES  = 128 * BROW_BYTES;        // 34816 (full w2[d])

// smem layout (dynamic)
static constexpr int SMEM_LABELS  = 0;                       // 128*8*4 = 4096
static constexpr int SMEM_EMB     = 4096;                    // 4096
static constexpr int SMEM_PK      = 8192;                    // 8192
static constexpr int SMEM_STATS   = 16384;                   // 128
static constexpr int SMEM_NMASK   = 16512;                   // 128*4 = 512
static constexpr int SMEM_A       = 17024;                   // 34816
static constexpr int SMEM_BT0     = 51840;                   // 34816
static constexpr int SMEM_BT1     = 86656;                   // 34816
static constexpr int SMEM_TOTAL   = 121472;                  // 1 CTA/SM

// Pre-converted fp16 w2, [d][k_out][h] row-major (== col-major B for the mma).
__device__ __align__(16) __half g_w2h[DDIMS * HDIM * HDIM];
// Fragment-ordered, log2e-scaled w1/b1: (d,t,q) -> cols {cb,cb+1,cb+8,cb+9},
// cb = 16t+2q. [0..255] = w, [256..511] = b.
__device__ __align__(16) float4 g_pk[512];
// Per-dim stats: [0..7] max(w1L), [8..15] min(w1L), [16..23] max(b1L)
__device__ float g_st[24];

__global__ void prep_w2_kernel(const float* __restrict__ w2) {
    int i = blockIdx.x * 256 + threadIdx.x;      // exactly 131072 elements
    g_w2h[i] = __float2half(w2[i]);
}

// 256 threads: lane l of warp d handles (t = l>>2, q = l&3).
__global__ void prep_small_kernel(const float* __restrict__ w1,
                                  const float* __restrict__ b1) {
    const int tid  = threadIdx.x;
    const int d    = tid >> 5;
    const int lane = tid & 31;
    const int t    = lane >> 2;
    const int q    = lane & 3;
    const int cb   = 16 * t + 2 * q;
    const float LOG2E = 1.44269504088896340736f;

    float w0  = w1[d * HDIM + cb]     * LOG2E;
    float w1v = w1[d * HDIM + cb + 1] * LOG2E;
    float w8  = w1[d * HDIM + cb + 8] * LOG2E;
    float w9  = w1[d * HDIM + cb + 9] * LOG2E;
    float bb0 = b1[d * HDIM + cb]     * LOG2E;
    float bb1 = b1[d * HDIM + cb + 1] * LOG2E;
    float bb8 = b1[d * HDIM + cb + 8] * LOG2E;
    float bb9 = b1[d * HDIM + cb + 9] * LOG2E;

    const int e = (d * 8 + t) * 4 + q;
    g_pk[e]       = make_float4(w0, w1v, w8, w9);
    g_pk[256 + e] = make_float4(bb0, bb1, bb8, bb9);

    float hi = fmaxf(fmaxf(w0, w1v), fmaxf(w8, w9));
    float lo = fminf(fminf(w0, w1v), fminf(w8, w9));
    float bm = fmaxf(fmaxf(bb0, bb1), fmaxf(bb8, bb9));
    #pragma unroll
    for (int s = 16; s; s >>= 1) {
        hi = fmaxf(hi, __shfl_xor_sync(0xffffffffu, hi, s));
        lo = fminf(lo, __shfl_xor_sync(0xffffffffu, lo, s));
        bm = fmaxf(bm, __shfl_xor_sync(0xffffffffu, bm, s));
    }
    if (lane == 0) { g_st[d] = hi; g_st[8 + d] = lo; g_st[16 + d] = bm; }
}

__device__ __forceinline__ uint32_t smem_to_u32(const void* p) {
    uint32_t a;
    asm("{ .reg .u64 t; cvta.to.shared.u64 t, %1; cvt.u32.u64 %0, t; }"
        : "=r"(a) : "l"(p));
    return a;
}

__device__ __forceinline__ float ex2f(float x) {
    float r;
    asm("ex2.approx.ftz.f32 %0, %1;" : "=f"(r) : "f"(x));
    return r;
}

__device__ __forceinline__ void cp_async16(uint32_t dst, const void* src) {
    asm volatile("cp.async.cg.shared.global [%0], [%1], 16;"
                 :: "r"(dst), "l"(src));
}

__global__ void __launch_bounds__(CTA_THREADS, 1)
cond_embed_kernel(const float* __restrict__ labels,
                  const float* __restrict__ emb_w,
                  const int*   __restrict__ uncond_p,
                  float*       __restrict__ out)
{
    extern __shared__ __align__(16) char smem[];
    float*  lab_sm = reinterpret_cast<float*>(smem + SMEM_LABELS);
    float*  emb_sm = reinterpret_cast<float*>(smem + SMEM_EMB);
    float4* pk_sm  = reinterpret_cast<float4*>(smem + SMEM_PK);
    float*  st_sm  = reinterpret_cast<float*>(smem + SMEM_STATS);
    int*    nm_sm  = reinterpret_cast<int*>(smem + SMEM_NMASK);

    const int tid  = threadIdx.x;
    const int wid  = tid >> 5;
    const int lane = tid & 31;
    const int gr   = lane >> 2;
    const int q    = lane & 3;
    const int blk  = blockIdx.x;

    const uint32_t smem_base = smem_to_u32(smem);

    // ---- stage labels + emb + pk + stats; B(0) (full 32KB) via cp.async ----
    for (int i = tid; i < 1024; i += CTA_THREADS) {
        lab_sm[i] = labels[(size_t)blk * 1024 + i];
        emb_sm[i] = emb_w[i];
    }
    for (int i = tid; i < 512; i += CTA_THREADS)
        pk_sm[i] = g_pk[i];
    if (tid < 24) st_sm[tid] = g_st[tid];
    {
        const char* src = reinterpret_cast<const char*>(g_w2h);
        #pragma unroll
        for (int i = 0; i < 4; ++i) {
            int idx = tid + i * CTA_THREADS;      // 0..2047, 16B lines
            cp_async16(smem_base + SMEM_BT0 + (idx >> 4) * BROW_BYTES
                       + (idx & 15) * 16, src + idx * 16);
        }
        asm volatile("cp.async.commit_group;" ::: "memory");
    }
    const int force_drop = *uncond_p;

    float acc[32];
    #pragma unroll
    for (int i = 0; i < 32; ++i) acc[i] = 0.0f;

    unsigned mask = 0;                         // drop bits for row srow
    const int srow  = 8 * wid + gr;            // softmax row owned by this lane (0..127)
    const int nh    = wid >> 3;                // output-column half of this warp
    const int mrow0 = 16 * (wid & 7);          // mma M-tile start row

    // ldmatrix lane bases
    const uint32_t a_lm = smem_base + SMEM_A
        + (uint32_t)(mrow0 + (lane & 15)) * BROW_BYTES
        + (uint32_t)((lane >> 4) & 1) * 16u;
    const uint32_t b_lm = smem_base + SMEM_BT0
        + (uint32_t)nh * (64u * BROW_BYTES)
        + ((uint32_t)(lane >> 4) * 8u + (uint32_t)(lane & 7)) * BROW_BYTES
        + (uint32_t)((lane >> 3) & 1) * 16u;
    // softmax fragment store base: row srow, byte cols 32t+4q (+16)
    const uint32_t a_st = smem_base + SMEM_A
        + (uint32_t)srow * BROW_BYTES + (uint32_t)(4 * q);

    __syncthreads();   // labels/pk/stats staged (B(0) still in flight)

    for (int d = 0; d < DDIMS; ++d) {
        // ---- 1. stage B(d+1) into the buffer mma(d-1) just vacated ----
        // (top-of-loop barrier from prev iteration guarantees the buffer and
        //  A-tile are no longer being read)
        if (d < DDIMS - 1) {
            const char* src = reinterpret_cast<const char*>(g_w2h + (d + 1) * HDIM * HDIM);
            const uint32_t dstb = smem_base + ((d + 1) & 1 ? SMEM_BT1 : SMEM_BT0);
            #pragma unroll
            for (int i = 0; i < 4; ++i) {
                int idx = tid + i * CTA_THREADS;
                cp_async16(dstb + (idx >> 4) * BROW_BYTES + (idx & 15) * 16,
                           src + idx * 16);
            }
            asm volatile("cp.async.commit_group;" ::: "memory");
        }

        // ---- 2. softmax for row srow -> 16 packed fp16x2 regs (once per d) ----
        uint32_t pk16[16];
        float inv;
        {
            const float x = lab_sm[srow * DDIMS + d];
            const bool dr = ((__float_as_uint(x) & 0x7fffffffu) > 0x7f800000u)
                            || force_drop;
            if (dr) mask |= 1u << d;
            const float xs = dr ? 0.0f : x;
            const float hiL = st_sm[d], loL = st_sm[8 + d], bmL = st_sm[16 + d];
            const float ub = fmaf(xs, xs >= 0.0f ? hiL : loL, bmL);
            const float4* pw = pk_sm + d * 32 + q;
            const float4* pb = pw + 256;
            float z = 0.0f;
            #pragma unroll
            for (int t = 0; t < 8; ++t) {
                const float4 wv = pw[t * 4];
                const float4 bv = pb[t * 4];
                float e0 = ex2f(fmaf(xs, wv.x, bv.x) - ub);
                float e1 = ex2f(fmaf(xs, wv.y, bv.y) - ub);
                float e2 = ex2f(fmaf(xs, wv.z, bv.z) - ub);
                float e3 = ex2f(fmaf(xs, wv.w, bv.w) - ub);
                z += (e0 + e1) + (e2 + e3);
                __half2 plo = __floats2half2_rn(e0, e1);
                __half2 phi = __floats2half2_rn(e2, e3);
                pk16[2 * t]     = *reinterpret_cast<uint32_t*>(&plo);
                pk16[2 * t + 1] = *reinterpret_cast<uint32_t*>(&phi);
            }
            z += __shfl_xor_sync(0xffffffffu, z, 1);
            z += __shfl_xor_sync(0xffffffffu, z, 2);
            inv = dr ? 0.0f : __fdividef(1.0f, z);
        }
        {
            const __half2 iv = __half2half2(__float2half_rn(inv));
            #pragma unroll
            for (int t = 0; t < 16; ++t) {
                __half2* a = reinterpret_cast<__half2*>(pk16 + t);
                *a = __hmul2(*a, iv);
            }
        }

        // ---- 3. store A(d) fragments (conflict-free: banks 4*gr+q distinct) ----
        #pragma unroll
        for (int t = 0; t < 8; ++t) {
            asm volatile("st.shared.u32 [%0], %1;"
                         :: "r"(a_st + (uint32_t)(32 * t)), "r"(pk16[2 * t]));
            asm volatile("st.shared.u32 [%0], %1;"
                         :: "r"(a_st + (uint32_t)(32 * t + 16)), "r"(pk16[2 * t + 1]));
        }

        // ---- 4. B(d) landed? (groups in flight: B(d+1) newest, B(d) older) ----
        if (d < DDIMS - 1)
            asm volatile("cp.async.wait_group 1;" ::: "memory");
        else
            asm volatile("cp.async.wait_group 0;" ::: "memory");

        __syncthreads();   // A(d) stores + B(d) visible to all warps

        // ---- 5. D += A(d) @ B(d)^T : 8 k-chunks, A via ldmatrix JIT ----
        const uint32_t bb = b_lm + (uint32_t)(d & 1) * BTILE_BYTES;
        #pragma unroll
        for (int t = 0; t < 8; ++t) {
            uint32_t af0, af1, af2, af3;
            asm volatile(
                "ldmatrix.sync.aligned.m8n8.x4.shared.b16 {%0,%1,%2,%3}, [%4];"
                : "=r"(af0), "=r"(af1), "=r"(af2), "=r"(af3)
                : "r"(a_lm + (uint32_t)t * 32u));
            #pragma unroll
            for (int p = 0; p < 4; ++p) {
                uint32_t bf0, bf1, bf2, bf3;
                asm volatile(
                    "ldmatrix.sync.aligned.m8n8.x4.shared.b16 {%0,%1,%2,%3}, [%4];"
                    : "=r"(bf0), "=r"(bf1), "=r"(bf2), "=r"(bf3)
                    : "r"(bb + (uint32_t)p * (16u * BROW_BYTES) + (uint32_t)t * 32u));
                asm volatile(
                    "mma.sync.aligned.m16n8k16.row.col.f32.f16.f16.f32 "
                    "{%0,%1,%2,%3}, {%4,%5,%6,%7}, {%8,%9}, {%0,%1,%2,%3};"
                    : "+f"(acc[8*p+0]), "+f"(acc[8*p+1]), "+f"(acc[8*p+2]), "+f"(acc[8*p+3])
                    : "r"(af0), "r"(af1), "r"(af2), "r"(af3), "r"(bf0), "r"(bf1));
                asm volatile(
                    "mma.sync.aligned.m16n8k16.row.col.f32.f16.f16.f32 "
                    "{%0,%1,%2,%3}, {%4,%5,%6,%7}, {%8,%9}, {%0,%1,%2,%3};"
                    : "+f"(acc[8*p+4]), "+f"(acc[8*p+5]), "+f"(acc[8*p+6]), "+f"(acc[8*p+7])
                    : "r"(af0), "r"(af1), "r"(af2), "r"(af3), "r"(bf2), "r"(bf3));
            }
        }

        __syncthreads();   // mma(d) reads done -> A-tile & alt B buffer reusable
    }

    // ---- publish drop masks, then epilogue ----
    if (q == 0) nm_sm[srow] = (int)mask;
    __syncthreads();

    const unsigned m0 = (unsigned)nm_sm[mrow0 + gr];
    const unsigned m1 = (unsigned)nm_sm[mrow0 + gr + 8];
    const size_t base0 = ((size_t)blk * ROWS_PER_CTA + mrow0 + gr) * HDIM + nh * 64;
    const size_t base1 = base0 + 8 * HDIM;
    #pragma unroll
    for (int p = 0; p < 4; ++p) {
        #pragma unroll
        for (int h = 0; h < 2; ++h) {            // nt = 2p+h
            const int c  = (2 * p + h) * 8 + 2 * q;
            const int ce = nh * 64 + c;
            float v0 = acc[8*p + 4*h + 0], v1 = acc[8*p + 4*h + 1];
            float v2 = acc[8*p + 4*h + 2], v3 = acc[8*p + 4*h + 3];
            unsigned m = m0;
            while (m) {
                const int dd = __ffs(m) - 1; m &= m - 1;
                v0 += emb_sm[dd * HDIM + ce];
                v1 += emb_sm[dd * HDIM + ce + 1];
            }
            m = m1;
            while (m) {
                const int dd = __ffs(m) - 1; m &= m - 1;
                v2 += emb_sm[dd * HDIM + ce];
                v3 += emb_sm[dd * HDIM + ce + 1];
            }
            *reinterpret_cast<float2*>(out + base0 + c) = make_float2(v0, v1);
            *reinterpret_cast<float2*>(out + base1 + c) = make_float2(v2, v3);
        }
    }
}

// ============================================================================
// kernel_launch — inputs: labels, emb_w, w1, b1, w2, train, unconditioned
//                 output: float32 [131072, 128]
// ============================================================================
extern "C" void kernel_launch(void* const* d_in, const int* in_sizes, int n_in,
                              void* d_out, int out_size)
{
    const float* labels = (const float*)d_in[0];
    const float* emb_w  = (const float*)d_in[1];
    const float* w1     = (const float*)d_in[2];
    const float* b1     = (const float*)d_in[3];
    const float* w2     = (const float*)d_in[4];
    const int*   uncond = (n_in > 6) ? (const int*)d_in[6] : (const int*)d_in[5];
    float* out = (float*)d_out;

    prep_w2_kernel<<<DDIMS * HDIM * HDIM / 256, 256>>>(w2);
    prep_small_kernel<<<1, 256>>>(w1, b1);

    cudaFuncSetAttribute(cond_embed_kernel,
                         cudaFuncAttributeMaxDynamicSharedMemorySize, SMEM_TOTAL);
    cond_embed_kernel<<<NBLOCKS, CTA_THREADS, SMEM_TOTAL>>>(
        labels, emb_w, uncond, out);
}